// round 12
// baseline (speedup 1.0000x reference)
#include <cuda_runtime.h>
#include <cuda_bf16.h>
#include <cstdint>

// Problem constants
#define Bn   96
#define Cn   128
#define Hn   64
#define Wn   128
#define HWn  (Hn * Wn)
#define TSn  16

#define Z_OFF  0
#define HC_OFF 786432
#define R_OFF  1572864

// -------- device scratch (no allocs allowed) --------
__device__ float g_wd[Bn * Cn * 9];
__device__ float g_part[4 * Bn * HWn];   // four channel-quarter partial planes
__device__ float g_gap[Bn * Cn];
__device__ float g_hdn[Bn * 576];
__device__ int   g_x0[Bn * TSn], g_x1[Bn * TSn], g_y0[Bn * TSn], g_y1[Bn * TSn];
__device__ float g_wx[Bn * TSn], g_wy[Bn * TSn];

// ============================================================
// Kernel 1: per-batch argmax over H_piece + sampling-grid precompute
// ============================================================
__global__ void __launch_bounds__(256) argmax_kernel(const float* __restrict__ hp) {
    __shared__ float sv[256];
    __shared__ int   si[256];
    int b = blockIdx.x;
    int tid = threadIdx.x;
    const float* p = hp + b * HWn;
    float best = -1e30f; int bi = 0x7fffffff;
    for (int i = tid; i < HWn; i += 256) {
        float v = p[i];
        if (v > best) { best = v; bi = i; }   // ascending keeps first occurrence
    }
    sv[tid] = best; si[tid] = bi;
    __syncthreads();
    for (int s = 128; s > 0; s >>= 1) {
        if (tid < s) {
            float ov = sv[tid + s]; int oi = si[tid + s];
            if (ov > sv[tid] || (ov == sv[tid] && oi < si[tid])) { sv[tid] = ov; si[tid] = oi; }
        }
        __syncthreads();
    }
    int am = si[0];
    if (tid < 16) {
        int j = tid;
        float u = (float)(am % Wn);
        float fx = (-7.5f + (float)j) + u * ((float)Wn / (float)(Wn - 1)) - 0.5f;
        fx = fminf(fmaxf(fx, 0.0f), (float)(Wn - 1));
        float x0 = floorf(fx);
        int x0i = (int)x0; if (x0i < 0) x0i = 0; if (x0i > Wn - 1) x0i = Wn - 1;
        int x1i = x0i + 1; if (x1i > Wn - 1) x1i = Wn - 1;
        g_x0[b * TSn + j] = x0i; g_x1[b * TSn + j] = x1i; g_wx[b * TSn + j] = fx - x0;
    } else if (tid < 32) {
        int i = tid - 16;
        float v = (float)(am / Wn);
        float fy = (-7.5f + (float)i) + v * ((float)Hn / (float)(Hn - 1)) - 0.5f;
        fy = fminf(fmaxf(fy, 0.0f), (float)(Hn - 1));
        float y0 = floorf(fy);
        int y0i = (int)y0; if (y0i < 0) y0i = 0; if (y0i > Hn - 1) y0i = Hn - 1;
        int y1i = y0i + 1; if (y1i > Hn - 1) y1i = Hn - 1;
        g_y0[b * TSn + i] = y0i; g_y1[b * TSn + i] = y1i; g_wy[b * TSn + i] = fy - y0;
    }
}

// ============================================================
// Kernel 2: bilinear extract (-> R, coalesced) + GAP (-> g_gap)
// ============================================================
__global__ void __launch_bounds__(256) extract_kernel(const float* __restrict__ Hf,
                                                      float* __restrict__ Rout) {
    __shared__ int   sx0[TSn], sx1[TSn], sy0[TSn], sy1[TSn];
    __shared__ float swx[TSn], swy[TSn];
    int b = blockIdx.y;
    int cq = blockIdx.x;
    int tid = threadIdx.x;
    int warp = tid >> 5, lane = tid & 31;

    if (tid < 16) {
        sx0[tid] = g_x0[b * TSn + tid];
        sx1[tid] = g_x1[b * TSn + tid];
        swx[tid] = g_wx[b * TSn + tid];
        sy0[tid] = g_y0[b * TSn + tid];
        sy1[tid] = g_y1[b * TSn + tid];
        swy[tid] = g_wy[b * TSn + tid];
    }
    __syncthreads();

    const float* img = Hf + (size_t)b * Cn * HWn;

    #pragma unroll
    for (int cc = 0; cc < 4; ++cc) {
        int c = cq * 32 + warp * 4 + cc;
        const float* q = img + (size_t)c * HWn;
        float vals[8];
        float sum = 0.0f;
        #pragma unroll
        for (int k = 0; k < 8; ++k) {
            int px = k * 32 + lane;
            int i = px >> 4, j = px & 15;
            float wx = swx[j], wy = swy[i];
            float v00 = q[sy0[i] * Wn + sx0[j]];
            float v01 = q[sy0[i] * Wn + sx1[j]];
            float v10 = q[sy1[i] * Wn + sx0[j]];
            float v11 = q[sy1[i] * Wn + sx1[j]];
            float val = v00 * (1.0f - wx) * (1.0f - wy)
                      + v01 * wx * (1.0f - wy)
                      + v10 * (1.0f - wx) * wy
                      + v11 * wx * wy;
            vals[k] = val;
            sum += val;
        }
        float* rb = Rout + ((size_t)b * Cn + c) * 256;
        #pragma unroll
        for (int k = 0; k < 8; ++k) rb[k * 32 + lane] = vals[k];
        #pragma unroll
        for (int off = 16; off > 0; off >>= 1) sum += __shfl_xor_sync(0xffffffffu, sum, off);
        if (lane == 0) g_gap[b * Cn + c] = sum * (1.0f / 256.0f);
    }
}

// ============================================================
// Kernel 3a: fc1(relu) -> g_hdn. grid = 96 blocks, 1024 threads.
// ============================================================
__global__ void __launch_bounds__(1024) fc1_kernel(const float* __restrict__ fc1w,
                                                   const float* __restrict__ fc1b) {
    __shared__ __align__(16) float s_gap[128];
    int b = blockIdx.x;
    int tid = threadIdx.x;
    int warp = tid >> 5, lane = tid & 31;

    if (tid < 128) s_gap[tid] = g_gap[b * Cn + tid];
    __syncthreads();

    const float4* g4 = (const float4*)s_gap;
    float4 g = g4[lane];
    #pragma unroll
    for (int og = 0; og < 18; og += 3) {
        int o0 = warp * 18 + og;
        float pr[3];
        #pragma unroll
        for (int t = 0; t < 3; ++t) {
            const float4* wrow = (const float4*)(fc1w + (size_t)(o0 + t) * 128);
            float4 w = wrow[lane];
            pr[t] = w.x * g.x + w.y * g.y + w.z * g.z + w.w * g.w;
        }
        #pragma unroll
        for (int t = 0; t < 3; ++t) {
            #pragma unroll
            for (int off = 16; off > 0; off >>= 1)
                pr[t] += __shfl_xor_sync(0xffffffffu, pr[t], off);
            if (lane == 0) g_hdn[b * 576 + o0 + t] = fmaxf(pr[t] + fc1b[o0 + t], 0.0f);
        }
    }
}

// ============================================================
// Kernel 3b: fc2 + 3x3 L2-norm, split by (output quarter, 4-batch group).
// grid = (4, 24), 1024 threads. Each block reads 288 fc2 rows (0.65MB)
// once and applies them to 4 batches -> 4x less L2 weight traffic.
// 288 outputs = exactly 32 channels -> norm stays block-local.
// ============================================================
__global__ void __launch_bounds__(1024) fc2_kernel(const float* __restrict__ fc2w,
                                                   const float* __restrict__ fc2b) {
    __shared__ __align__(16) float s_hdn[4][576];
    __shared__ float s_kp[4][288];
    int q = blockIdx.x;           // output quarter (0..3)
    int b0 = blockIdx.y * 4;      // batch group
    int tid = threadIdx.x;
    int warp = tid >> 5, lane = tid & 31;

    for (int idx = tid; idx < 4 * 576; idx += 1024) {
        int bb = idx / 576, o = idx - bb * 576;
        s_hdn[bb][o] = g_hdn[(b0 + bb) * 576 + o];
    }
    __syncthreads();

    const float4* h0 = (const float4*)s_hdn[0];
    const float4* h1 = (const float4*)s_hdn[1];
    const float4* h2 = (const float4*)s_hdn[2];
    const float4* h3 = (const float4*)s_hdn[3];

    // 288 outputs, 9 per warp; 4 batches per output
    #pragma unroll 1
    for (int og = 0; og < 9; ++og) {
        int ol = warp * 9 + og;           // local output 0..287
        int o = q * 288 + ol;
        const float4* wrow = (const float4*)(fc2w + (size_t)o * 576);
        float p0 = 0.f, p1 = 0.f, p2 = 0.f, p3 = 0.f;
        #pragma unroll
        for (int j = 0; j < 5; ++j) {
            int idx = lane + 32 * j;
            if (idx < 144) {
                float4 w = wrow[idx];
                float4 a = h0[idx];
                float4 bq = h1[idx];
                float4 cq2 = h2[idx];
                float4 dq = h3[idx];
                p0 += w.x * a.x + w.y * a.y + w.z * a.z + w.w * a.w;
                p1 += w.x * bq.x + w.y * bq.y + w.z * bq.z + w.w * bq.w;
                p2 += w.x * cq2.x + w.y * cq2.y + w.z * cq2.z + w.w * cq2.w;
                p3 += w.x * dq.x + w.y * dq.y + w.z * dq.z + w.w * dq.w;
            }
        }
        #pragma unroll
        for (int off = 16; off > 0; off >>= 1) {
            p0 += __shfl_xor_sync(0xffffffffu, p0, off);
            p1 += __shfl_xor_sync(0xffffffffu, p1, off);
            p2 += __shfl_xor_sync(0xffffffffu, p2, off);
            p3 += __shfl_xor_sync(0xffffffffu, p3, off);
        }
        if (lane == 0) {
            float bsv = fc2b[o];
            s_kp[0][ol] = p0 + bsv;
            s_kp[1][ol] = p1 + bsv;
            s_kp[2][ol] = p2 + bsv;
            s_kp[3][ol] = p3 + bsv;
        }
    }
    __syncthreads();

    // norm: 32 local channels x 4 batches = 128 slots
    if (tid < 128) {
        int bb = tid >> 5, cl = tid & 31;
        int cg = q * 32 + cl;             // global channel
        float v[9]; float nrm = 0.0f;
        #pragma unroll
        for (int k = 0; k < 9; ++k) { v[k] = s_kp[bb][cl * 9 + k]; nrm = fmaf(v[k], v[k], nrm); }
        nrm = sqrtf(nrm);
        float inv = 1.0f / fmaxf(nrm, 1e-12f);
        #pragma unroll
        for (int k = 0; k < 9; ++k) g_wd[(b0 + bb) * 1152 + cg * 9 + k] = v[k] * inv;
    }
}

// ============================================================
// Kernel 4 (v3, best known): 32-channel quarter, 32-row tile,
// 256 threads; thread = 4 px (x) x 4 rows (y). 3-slot cp.async ring.
// grid (8,96): bit0 = y-tile, bits[1:2] = quarter.
// ============================================================
#define BUF_ROWS   34
#define BUF_STRIDE 136
#define BUF_FLOATS (BUF_ROWS * BUF_STRIDE)   // 4624
#define WS_OFF     (3 * BUF_FLOATS)          // 13872
#define CORR_SMEM  ((WS_OFF + 32 * 12) * 4)  // 57024 bytes
#define CH_Q       32

__device__ __forceinline__ void cp16(float* dst, const float* src) {
    unsigned sa = (unsigned)__cvta_generic_to_shared(dst);
    asm volatile("cp.async.cg.shared.global [%0], [%1], 16;\n" :: "r"(sa), "l"(src));
}

__device__ __forceinline__ void corr_issue(float* bufs, const float* Hb,
                                           int c, int slot, int ybase, int tid) {
    const float* src = Hb + (size_t)c * HWn;
    float* dstbase = bufs + slot * BUF_FLOATS;
    #pragma unroll
    for (int it = 0; it < 5; ++it) {
        int idx = tid + it * 256;
        if (idx < BUF_ROWS * 32) {
            int r = idx >> 5, g = idx & 31;
            int yimg = ybase - 1 + r;
            if ((unsigned)yimg < (unsigned)Hn) {
                cp16(dstbase + r * BUF_STRIDE + 4 + g * 4, src + yimg * Wn + g * 4);
            }
        }
    }
    asm volatile("cp.async.commit_group;\n");
}

__global__ void __launch_bounds__(256, 4) corr_kernel(const float* __restrict__ Hf) {
    extern __shared__ __align__(16) float dsm[];
    float* bufs = dsm;
    float* ws   = dsm + WS_OFF;

    int b = blockIdx.y;
    int ybase = (blockIdx.x & 1) * 32;
    int cq = blockIdx.x >> 1;           // 0..3
    int tid = threadIdx.x;
    int xg = tid & 31;                  // 4-px column group
    int ys = tid >> 5;                  // 0..7, 4 rows each

    {
        float4* d4 = (float4*)dsm;
        #pragma unroll
        for (int it = 0; it < 14; ++it) {
            int i = tid + it * 256;
            if (i < WS_OFF / 4) d4[i] = make_float4(0.f, 0.f, 0.f, 0.f);
        }
    }
    for (int i = tid; i < CH_Q * 9; i += 256) {
        int c = i / 9, k = i - c * 9;
        ws[c * 12 + k] = g_wd[b * 1152 + cq * (CH_Q * 9) + i];
    }
    if (tid < CH_Q * 3) {
        ws[(tid / 3) * 12 + 9 + (tid % 3)] = 0.0f;
    }
    __syncthreads();

    const float* Hb = Hf + (size_t)b * Cn * HWn + (size_t)cq * CH_Q * HWn;

    corr_issue(bufs, Hb, 0, 0, ybase, tid);
    corr_issue(bufs, Hb, 1, 1, ybase, tid);

    float acc[4][4];
    #pragma unroll
    for (int o = 0; o < 4; ++o)
        #pragma unroll
        for (int j = 0; j < 4; ++j) acc[o][j] = 0.0f;

    const float4* ws4 = (const float4*)ws;

    for (int c = 0; c < CH_Q; ++c) {
        if (c < CH_Q - 1) { asm volatile("cp.async.wait_group 1;\n" ::: "memory"); }
        else              { asm volatile("cp.async.wait_group 0;\n" ::: "memory"); }
        __syncthreads();
        if (c + 2 < CH_Q) corr_issue(bufs, Hb, c + 2, (c + 2) % 3, ybase, tid);

        float4 wA = ws4[c * 3 + 0];
        float4 wB = ws4[c * 3 + 1];
        float4 wC = ws4[c * 3 + 2];
        float w0 = wA.x, w1 = wA.y, w2 = wA.z, w3 = wA.w;
        float w4 = wB.x, w5 = wB.y, w6 = wB.z, w7 = wB.w;
        float w8 = wC.x;

        const float* S = bufs + (c % 3) * BUF_FLOATS + (ys * 4) * BUF_STRIDE + 4 + 4 * xg;

        #pragma unroll
        for (int r = 0; r < 6; ++r) {
            const float* row = S + r * BUF_STRIDE;
            float4 m = *(const float4*)row;
            float lf = row[-1];
            float rt = row[4];
            #pragma unroll
            for (int wr = 0; wr < 3; ++wr) {
                int o = r - wr;
                if (o >= 0 && o <= 3) {
                    float t0, t1, t2;
                    if (wr == 0) { t0 = w0; t1 = w1; t2 = w2; }
                    else if (wr == 1) { t0 = w3; t1 = w4; t2 = w5; }
                    else { t0 = w6; t1 = w7; t2 = w8; }
                    acc[o][0] = fmaf(lf,  t0, fmaf(m.x, t1, fmaf(m.y, t2, acc[o][0])));
                    acc[o][1] = fmaf(m.x, t0, fmaf(m.y, t1, fmaf(m.z, t2, acc[o][1])));
                    acc[o][2] = fmaf(m.y, t0, fmaf(m.z, t1, fmaf(m.w, t2, acc[o][2])));
                    acc[o][3] = fmaf(m.z, t0, fmaf(m.w, t1, fmaf(rt,  t2, acc[o][3])));
                }
            }
        }
    }

    float* pout = g_part + (size_t)cq * Bn * HWn + (size_t)b * HWn;
    int y0 = ybase + ys * 4;
    #pragma unroll
    for (int o = 0; o < 4; ++o) {
        float4 v = make_float4(acc[o][0], acc[o][1], acc[o][2], acc[o][3]);
        *(float4*)(pout + (y0 + o) * Wn + 4 * xg) = v;
    }
}

// ============================================================
// Kernel 5 (v5): lane = filter-channel warp-GEMV fuse, 4-ROW TILES,
// vectorized taps: per 4 px per tap-row, 1 LDS.128 + 2 scalar LDS
// (shifted windows built in registers) instead of 12 broadcast LDS.
// grid (16,96) = 1536 blocks. 256 threads.
// ============================================================
#define FT_ROWS   6
#define FT_STRIDE 136
#define FT_FLOATS (FT_ROWS * FT_STRIDE)  // 816

__device__ __forceinline__ float fast_sigmoid(float v) {
    return __fdividef(1.0f, 1.0f + __expf(-v));
}

__global__ void __launch_bounds__(256) fuse_kernel(const float* __restrict__ Hg,
                                                   const float* __restrict__ c1w,
                                                   const float* __restrict__ c1b,
                                                   const float* __restrict__ bng,
                                                   const float* __restrict__ bnb,
                                                   const float* __restrict__ bnm,
                                                   const float* __restrict__ bnv,
                                                   const float* __restrict__ c2w,
                                                   const float* __restrict__ c2b,
                                                   float* __restrict__ hc,
                                                   float* __restrict__ zout) {
    __shared__ __align__(16) float tg[FT_FLOATS];
    __shared__ __align__(16) float tc[FT_FLOATS];

    int b = blockIdx.y;
    int ybase = blockIdx.x * 4;
    int tid = threadIdx.x;
    int warp = tid >> 5, lane = tid & 31;

    int f = lane;
    float s    = bng[f] * rsqrtf(bnv[f] + 1e-5f);
    float bias = (c1b[f] - bnm[f]) * s + bnb[f];
    float c2f  = c2w[f];
    float sb2  = c2b[0];
    float w[18];
    #pragma unroll
    for (int t = 0; t < 18; ++t) w[t] = c1w[f * 18 + t] * s;

    for (int i = tid; i < FT_FLOATS; i += 256) { tg[i] = 0.0f; tc[i] = 0.0f; }
    __syncthreads();

    const float* p0 = g_part + (size_t)b * HWn;
    const float* p1 = g_part + (size_t)1 * Bn * HWn + (size_t)b * HWn;
    const float* p2 = g_part + (size_t)2 * Bn * HWn + (size_t)b * HWn;
    const float* p3 = g_part + (size_t)3 * Bn * HWn + (size_t)b * HWn;

    for (int idx = tid; idx < FT_ROWS * Wn; idx += 256) {
        int r = idx >> 7, xx = idx & 127;
        int yimg = ybase - 1 + r;
        if ((unsigned)yimg < (unsigned)Hn) {
            int goff = b * HWn + yimg * Wn + xx;
            int loff = yimg * Wn + xx;
            tg[r * FT_STRIDE + 4 + xx] = Hg[goff];
            float sum = (p0[loff] + p1[loff]) + (p2[loff] + p3[loff]);
            float sig = fast_sigmoid(sum);
            tc[r * FT_STRIDE + 4 + xx] = sig;
            if (yimg >= ybase && yimg < ybase + 4) hc[goff] = sig;
        }
    }
    __syncthreads();

    // warp handles tile-local row (warp>>1), column half (warp&1)
    int row = warp >> 1;                // 0..3
    int xh = warp & 1;                  // 0..1
    float* zr = zout + b * HWn + (ybase + row) * Wn;

    #pragma unroll 1
    for (int gi = 0; gi < 2; ++gi) {
        int cb = (xh * 2 + gi) * 32;
        float okeep = 0.0f;
        #pragma unroll 1
        for (int jq = 0; jq < 32; jq += 4) {
            float a0 = bias, a1 = bias, a2 = bias, a3 = bias;
            int c0 = cb + jq;
            #pragma unroll
            for (int half = 0; half < 2; ++half) {
                const float* pl = half ? tc : tg;
                #pragma unroll
                for (int dr = 0; dr < 3; ++dr) {
                    const float* rowp = pl + (row + dr) * FT_STRIDE + 4 + c0;
                    float4 m = *(const float4*)rowp;
                    float lf = rowp[-1];
                    float rt = rowp[4];
                    float t0 = w[half * 9 + dr * 3 + 0];
                    float t1 = w[half * 9 + dr * 3 + 1];
                    float t2 = w[half * 9 + dr * 3 + 2];
                    a0 = fmaf(lf,  t0, fmaf(m.x, t1, fmaf(m.y, t2, a0)));
                    a1 = fmaf(m.x, t0, fmaf(m.y, t1, fmaf(m.z, t2, a1)));
                    a2 = fmaf(m.y, t0, fmaf(m.z, t1, fmaf(m.w, t2, a2)));
                    a3 = fmaf(m.z, t0, fmaf(m.w, t1, fmaf(rt,  t2, a3)));
                }
            }
            float z0 = c2f * (a0 * fast_sigmoid(a0));
            float z1 = c2f * (a1 * fast_sigmoid(a1));
            float z2 = c2f * (a2 * fast_sigmoid(a2));
            float z3 = c2f * (a3 * fast_sigmoid(a3));
            #pragma unroll
            for (int off = 16; off > 0; off >>= 1) {
                z0 += __shfl_xor_sync(0xffffffffu, z0, off);
                z1 += __shfl_xor_sync(0xffffffffu, z1, off);
                z2 += __shfl_xor_sync(0xffffffffu, z2, off);
                z3 += __shfl_xor_sync(0xffffffffu, z3, off);
            }
            float o0 = fast_sigmoid(z0 + sb2);
            float o1 = fast_sigmoid(z1 + sb2);
            float o2 = fast_sigmoid(z2 + sb2);
            float o3 = fast_sigmoid(z3 + sb2);
            if (lane == jq + 0) okeep = o0;
            if (lane == jq + 1) okeep = o1;
            if (lane == jq + 2) okeep = o2;
            if (lane == jq + 3) okeep = o3;
        }
        zr[cb + lane] = okeep;
    }
}

// ============================================================
extern "C" void kernel_launch(void* const* d_in, const int* in_sizes, int n_in,
                              void* d_out, int out_size) {
    const float* Hf   = (const float*)d_in[0];
    const float* hp   = (const float*)d_in[1];
    const float* Hg   = (const float*)d_in[2];
    const float* fc1w = (const float*)d_in[3];
    const float* fc1b = (const float*)d_in[4];
    const float* fc2w = (const float*)d_in[5];
    const float* fc2b = (const float*)d_in[6];
    const float* c1w  = (const float*)d_in[7];
    const float* c1b  = (const float*)d_in[8];
    const float* bng  = (const float*)d_in[9];
    const float* bnb  = (const float*)d_in[10];
    const float* bnm  = (const float*)d_in[11];
    const float* bnv  = (const float*)d_in[12];
    const float* c2w  = (const float*)d_in[13];
    const float* c2b  = (const float*)d_in[14];

    float* out = (float*)d_out;
    float* z  = out + Z_OFF;
    float* hc = out + HC_OFF;
    float* R  = out + R_OFF;

    argmax_kernel<<<Bn, 256>>>(hp);
    extract_kernel<<<dim3(4, Bn), 256>>>(Hf, R);
    fc1_kernel<<<Bn, 1024>>>(fc1w, fc1b);
    fc2_kernel<<<dim3(4, 24), 1024>>>(fc2w, fc2b);

    cudaFuncSetAttribute(corr_kernel, cudaFuncAttributeMaxDynamicSharedMemorySize, CORR_SMEM);
    corr_kernel<<<dim3(8, Bn), 256, CORR_SMEM>>>(Hf);

    fuse_kernel<<<dim3(16, Bn), 256>>>(Hg, c1w, c1b, bng, bnb, bnm, bnv, c2w, c2b, hc, z);
}

// round 13
// speedup vs baseline: 1.0300x; 1.0300x over previous
#include <cuda_runtime.h>
#include <cuda_bf16.h>
#include <cstdint>

// Problem constants
#define Bn   96
#define Cn   128
#define Hn   64
#define Wn   128
#define HWn  (Hn * Wn)
#define TSn  16

#define Z_OFF  0
#define HC_OFF 786432
#define R_OFF  1572864

// -------- device scratch (no allocs allowed) --------
__device__ float g_wd[Bn * Cn * 9];
__device__ float g_part[4 * Bn * HWn];   // four channel-quarter partial planes
__device__ float g_gap[Bn * Cn];
__device__ int   g_x0[Bn * TSn], g_x1[Bn * TSn], g_y0[Bn * TSn], g_y1[Bn * TSn];
__device__ float g_wx[Bn * TSn], g_wy[Bn * TSn];

// ============================================================
// Kernel 1: per-batch argmax over H_piece + sampling-grid precompute
// ============================================================
__global__ void __launch_bounds__(256) argmax_kernel(const float* __restrict__ hp) {
    __shared__ float sv[256];
    __shared__ int   si[256];
    int b = blockIdx.x;
    int tid = threadIdx.x;
    const float* p = hp + b * HWn;
    float best = -1e30f; int bi = 0x7fffffff;
    for (int i = tid; i < HWn; i += 256) {
        float v = p[i];
        if (v > best) { best = v; bi = i; }   // ascending keeps first occurrence
    }
    sv[tid] = best; si[tid] = bi;
    __syncthreads();
    for (int s = 128; s > 0; s >>= 1) {
        if (tid < s) {
            float ov = sv[tid + s]; int oi = si[tid + s];
            if (ov > sv[tid] || (ov == sv[tid] && oi < si[tid])) { sv[tid] = ov; si[tid] = oi; }
        }
        __syncthreads();
    }
    int am = si[0];
    if (tid < 16) {
        int j = tid;
        float u = (float)(am % Wn);
        float fx = (-7.5f + (float)j) + u * ((float)Wn / (float)(Wn - 1)) - 0.5f;
        fx = fminf(fmaxf(fx, 0.0f), (float)(Wn - 1));
        float x0 = floorf(fx);
        int x0i = (int)x0; if (x0i < 0) x0i = 0; if (x0i > Wn - 1) x0i = Wn - 1;
        int x1i = x0i + 1; if (x1i > Wn - 1) x1i = Wn - 1;
        g_x0[b * TSn + j] = x0i; g_x1[b * TSn + j] = x1i; g_wx[b * TSn + j] = fx - x0;
    } else if (tid < 32) {
        int i = tid - 16;
        float v = (float)(am / Wn);
        float fy = (-7.5f + (float)i) + v * ((float)Hn / (float)(Hn - 1)) - 0.5f;
        fy = fminf(fmaxf(fy, 0.0f), (float)(Hn - 1));
        float y0 = floorf(fy);
        int y0i = (int)y0; if (y0i < 0) y0i = 0; if (y0i > Hn - 1) y0i = Hn - 1;
        int y1i = y0i + 1; if (y1i > Hn - 1) y1i = Hn - 1;
        g_y0[b * TSn + i] = y0i; g_y1[b * TSn + i] = y1i; g_wy[b * TSn + i] = fy - y0;
    }
}

// ============================================================
// Kernel 2: bilinear extract (-> R, coalesced) + GAP (-> g_gap)
// ============================================================
__global__ void __launch_bounds__(256) extract_kernel(const float* __restrict__ Hf,
                                                      float* __restrict__ Rout) {
    __shared__ int   sx0[TSn], sx1[TSn], sy0[TSn], sy1[TSn];
    __shared__ float swx[TSn], swy[TSn];
    int b = blockIdx.y;
    int cq = blockIdx.x;
    int tid = threadIdx.x;
    int warp = tid >> 5, lane = tid & 31;

    if (tid < 16) {
        sx0[tid] = g_x0[b * TSn + tid];
        sx1[tid] = g_x1[b * TSn + tid];
        swx[tid] = g_wx[b * TSn + tid];
        sy0[tid] = g_y0[b * TSn + tid];
        sy1[tid] = g_y1[b * TSn + tid];
        swy[tid] = g_wy[b * TSn + tid];
    }
    __syncthreads();

    const float* img = Hf + (size_t)b * Cn * HWn;

    #pragma unroll
    for (int cc = 0; cc < 4; ++cc) {
        int c = cq * 32 + warp * 4 + cc;
        const float* q = img + (size_t)c * HWn;
        float vals[8];
        float sum = 0.0f;
        #pragma unroll
        for (int k = 0; k < 8; ++k) {
            int px = k * 32 + lane;
            int i = px >> 4, j = px & 15;
            float wx = swx[j], wy = swy[i];
            float v00 = q[sy0[i] * Wn + sx0[j]];
            float v01 = q[sy0[i] * Wn + sx1[j]];
            float v10 = q[sy1[i] * Wn + sx0[j]];
            float v11 = q[sy1[i] * Wn + sx1[j]];
            float val = v00 * (1.0f - wx) * (1.0f - wy)
                      + v01 * wx * (1.0f - wy)
                      + v10 * (1.0f - wx) * wy
                      + v11 * wx * wy;
            vals[k] = val;
            sum += val;
        }
        float* rb = Rout + ((size_t)b * Cn + c) * 256;
        #pragma unroll
        for (int k = 0; k < 8; ++k) rb[k * 32 + lane] = vals[k];
        #pragma unroll
        for (int off = 16; off > 0; off >>= 1) sum += __shfl_xor_sync(0xffffffffu, sum, off);
        if (lane == 0) g_gap[b * Cn + c] = sum * (1.0f / 256.0f);
    }
}

// ============================================================
// Kernel 3 (combined, reverted): fc1(relu) -> fc2 -> 3x3 L2-norm
// grid = 96 blocks, 1024 threads
// ============================================================
__global__ void __launch_bounds__(1024) fc_kernel(const float* __restrict__ fc1w,
                                                  const float* __restrict__ fc1b,
                                                  const float* __restrict__ fc2w,
                                                  const float* __restrict__ fc2b) {
    __shared__ __align__(16) float s_gap[128];
    __shared__ __align__(16) float s_hdn[576];
    __shared__ float s_kp[1152];
    int b = blockIdx.x;
    int tid = threadIdx.x;
    int warp = tid >> 5, lane = tid & 31;

    if (tid < 128) s_gap[tid] = g_gap[b * Cn + tid];
    __syncthreads();

    {
        const float4* g4 = (const float4*)s_gap;
        float4 g = g4[lane];
        #pragma unroll
        for (int og = 0; og < 18; og += 3) {
            int o0 = warp * 18 + og;
            float pr[3];
            #pragma unroll
            for (int t = 0; t < 3; ++t) {
                const float4* wrow = (const float4*)(fc1w + (size_t)(o0 + t) * 128);
                float4 w = wrow[lane];
                pr[t] = w.x * g.x + w.y * g.y + w.z * g.z + w.w * g.w;
            }
            #pragma unroll
            for (int t = 0; t < 3; ++t) {
                #pragma unroll
                for (int off = 16; off > 0; off >>= 1)
                    pr[t] += __shfl_xor_sync(0xffffffffu, pr[t], off);
                if (lane == 0) s_hdn[o0 + t] = fmaxf(pr[t] + fc1b[o0 + t], 0.0f);
            }
        }
    }
    __syncthreads();

    {
        const float4* h4 = (const float4*)s_hdn;     // 144 float4
        #pragma unroll
        for (int og = 0; og < 36; og += 4) {
            int o0 = warp * 36 + og;
            float pr[4];
            #pragma unroll
            for (int t = 0; t < 4; ++t) {
                const float4* wrow = (const float4*)(fc2w + (size_t)(o0 + t) * 576);
                float s = 0.0f;
                #pragma unroll
                for (int j = 0; j < 5; ++j) {
                    int idx = lane + 32 * j;
                    if (idx < 144) {
                        float4 w = wrow[idx];
                        float4 h = h4[idx];
                        s += w.x * h.x + w.y * h.y + w.z * h.z + w.w * h.w;
                    }
                }
                pr[t] = s;
            }
            #pragma unroll
            for (int t = 0; t < 4; ++t) {
                #pragma unroll
                for (int off = 16; off > 0; off >>= 1)
                    pr[t] += __shfl_xor_sync(0xffffffffu, pr[t], off);
                if (lane == 0) s_kp[o0 + t] = pr[t] + fc2b[o0 + t];
            }
        }
    }
    __syncthreads();

    if (tid < 128) {
        int c = tid;
        float v[9]; float nrm = 0.0f;
        #pragma unroll
        for (int k = 0; k < 9; ++k) { v[k] = s_kp[c * 9 + k]; nrm = fmaf(v[k], v[k], nrm); }
        nrm = sqrtf(nrm);
        float inv = 1.0f / fmaxf(nrm, 1e-12f);
        #pragma unroll
        for (int k = 0; k < 9; ++k) g_wd[b * 1152 + c * 9 + k] = v[k] * inv;
    }
}

// ============================================================
// Kernel 4 (v3, best known): 32-channel quarter, 32-row tile,
// 256 threads; thread = 4 px (x) x 4 rows (y). 3-slot cp.async ring.
// grid (8,96): bit0 = y-tile, bits[1:2] = quarter.
// ============================================================
#define BUF_ROWS   34
#define BUF_STRIDE 136
#define BUF_FLOATS (BUF_ROWS * BUF_STRIDE)   // 4624
#define WS_OFF     (3 * BUF_FLOATS)          // 13872
#define CORR_SMEM  ((WS_OFF + 32 * 12) * 4)  // 57024 bytes
#define CH_Q       32

__device__ __forceinline__ void cp16(float* dst, const float* src) {
    unsigned sa = (unsigned)__cvta_generic_to_shared(dst);
    asm volatile("cp.async.cg.shared.global [%0], [%1], 16;\n" :: "r"(sa), "l"(src));
}

__device__ __forceinline__ void corr_issue(float* bufs, const float* Hb,
                                           int c, int slot, int ybase, int tid) {
    const float* src = Hb + (size_t)c * HWn;
    float* dstbase = bufs + slot * BUF_FLOATS;
    #pragma unroll
    for (int it = 0; it < 5; ++it) {
        int idx = tid + it * 256;
        if (idx < BUF_ROWS * 32) {
            int r = idx >> 5, g = idx & 31;
            int yimg = ybase - 1 + r;
            if ((unsigned)yimg < (unsigned)Hn) {
                cp16(dstbase + r * BUF_STRIDE + 4 + g * 4, src + yimg * Wn + g * 4);
            }
        }
    }
    asm volatile("cp.async.commit_group;\n");
}

__global__ void __launch_bounds__(256, 4) corr_kernel(const float* __restrict__ Hf) {
    extern __shared__ __align__(16) float dsm[];
    float* bufs = dsm;
    float* ws   = dsm + WS_OFF;

    int b = blockIdx.y;
    int ybase = (blockIdx.x & 1) * 32;
    int cq = blockIdx.x >> 1;           // 0..3
    int tid = threadIdx.x;
    int xg = tid & 31;                  // 4-px column group
    int ys = tid >> 5;                  // 0..7, 4 rows each

    {
        float4* d4 = (float4*)dsm;
        #pragma unroll
        for (int it = 0; it < 14; ++it) {
            int i = tid + it * 256;
            if (i < WS_OFF / 4) d4[i] = make_float4(0.f, 0.f, 0.f, 0.f);
        }
    }
    for (int i = tid; i < CH_Q * 9; i += 256) {
        int c = i / 9, k = i - c * 9;
        ws[c * 12 + k] = g_wd[b * 1152 + cq * (CH_Q * 9) + i];
    }
    if (tid < CH_Q * 3) {
        ws[(tid / 3) * 12 + 9 + (tid % 3)] = 0.0f;
    }
    __syncthreads();

    const float* Hb = Hf + (size_t)b * Cn * HWn + (size_t)cq * CH_Q * HWn;

    corr_issue(bufs, Hb, 0, 0, ybase, tid);
    corr_issue(bufs, Hb, 1, 1, ybase, tid);

    float acc[4][4];
    #pragma unroll
    for (int o = 0; o < 4; ++o)
        #pragma unroll
        for (int j = 0; j < 4; ++j) acc[o][j] = 0.0f;

    const float4* ws4 = (const float4*)ws;

    for (int c = 0; c < CH_Q; ++c) {
        if (c < CH_Q - 1) { asm volatile("cp.async.wait_group 1;\n" ::: "memory"); }
        else              { asm volatile("cp.async.wait_group 0;\n" ::: "memory"); }
        __syncthreads();
        if (c + 2 < CH_Q) corr_issue(bufs, Hb, c + 2, (c + 2) % 3, ybase, tid);

        float4 wA = ws4[c * 3 + 0];
        float4 wB = ws4[c * 3 + 1];
        float4 wC = ws4[c * 3 + 2];
        float w0 = wA.x, w1 = wA.y, w2 = wA.z, w3 = wA.w;
        float w4 = wB.x, w5 = wB.y, w6 = wB.z, w7 = wB.w;
        float w8 = wC.x;

        const float* S = bufs + (c % 3) * BUF_FLOATS + (ys * 4) * BUF_STRIDE + 4 + 4 * xg;

        #pragma unroll
        for (int r = 0; r < 6; ++r) {
            const float* row = S + r * BUF_STRIDE;
            float4 m = *(const float4*)row;
            float lf = row[-1];
            float rt = row[4];
            #pragma unroll
            for (int wr = 0; wr < 3; ++wr) {
                int o = r - wr;
                if (o >= 0 && o <= 3) {
                    float t0, t1, t2;
                    if (wr == 0) { t0 = w0; t1 = w1; t2 = w2; }
                    else if (wr == 1) { t0 = w3; t1 = w4; t2 = w5; }
                    else { t0 = w6; t1 = w7; t2 = w8; }
                    acc[o][0] = fmaf(lf,  t0, fmaf(m.x, t1, fmaf(m.y, t2, acc[o][0])));
                    acc[o][1] = fmaf(m.x, t0, fmaf(m.y, t1, fmaf(m.z, t2, acc[o][1])));
                    acc[o][2] = fmaf(m.y, t0, fmaf(m.z, t1, fmaf(m.w, t2, acc[o][2])));
                    acc[o][3] = fmaf(m.z, t0, fmaf(m.w, t1, fmaf(rt,  t2, acc[o][3])));
                }
            }
        }
    }

    float* pout = g_part + (size_t)cq * Bn * HWn + (size_t)b * HWn;
    int y0 = ybase + ys * 4;
    #pragma unroll
    for (int o = 0; o < 4; ++o) {
        float4 v = make_float4(acc[o][0], acc[o][1], acc[o][2], acc[o][3]);
        *(float4*)(pout + (y0 + o) * Wn + 4 * xg) = v;
    }
}

// ============================================================
// Kernel 5 (v5, kept): lane = filter-channel warp-GEMV fuse, 4-ROW TILES,
// vectorized taps (LDS.128 + 2 scalar per tap-row per 4 px).
// grid (16,96) = 1536 blocks. 256 threads.
// ============================================================
#define FT_ROWS   6
#define FT_STRIDE 136
#define FT_FLOATS (FT_ROWS * FT_STRIDE)  // 816

__device__ __forceinline__ float fast_sigmoid(float v) {
    return __fdividef(1.0f, 1.0f + __expf(-v));
}

__global__ void __launch_bounds__(256) fuse_kernel(const float* __restrict__ Hg,
                                                   const float* __restrict__ c1w,
                                                   const float* __restrict__ c1b,
                                                   const float* __restrict__ bng,
                                                   const float* __restrict__ bnb,
                                                   const float* __restrict__ bnm,
                                                   const float* __restrict__ bnv,
                                                   const float* __restrict__ c2w,
                                                   const float* __restrict__ c2b,
                                                   float* __restrict__ hc,
                                                   float* __restrict__ zout) {
    __shared__ __align__(16) float tg[FT_FLOATS];
    __shared__ __align__(16) float tc[FT_FLOATS];

    int b = blockIdx.y;
    int ybase = blockIdx.x * 4;
    int tid = threadIdx.x;
    int warp = tid >> 5, lane = tid & 31;

    int f = lane;
    float s    = bng[f] * rsqrtf(bnv[f] + 1e-5f);
    float bias = (c1b[f] - bnm[f]) * s + bnb[f];
    float c2f  = c2w[f];
    float sb2  = c2b[0];
    float w[18];
    #pragma unroll
    for (int t = 0; t < 18; ++t) w[t] = c1w[f * 18 + t] * s;

    for (int i = tid; i < FT_FLOATS; i += 256) { tg[i] = 0.0f; tc[i] = 0.0f; }
    __syncthreads();

    const float* p0 = g_part + (size_t)b * HWn;
    const float* p1 = g_part + (size_t)1 * Bn * HWn + (size_t)b * HWn;
    const float* p2 = g_part + (size_t)2 * Bn * HWn + (size_t)b * HWn;
    const float* p3 = g_part + (size_t)3 * Bn * HWn + (size_t)b * HWn;

    for (int idx = tid; idx < FT_ROWS * Wn; idx += 256) {
        int r = idx >> 7, xx = idx & 127;
        int yimg = ybase - 1 + r;
        if ((unsigned)yimg < (unsigned)Hn) {
            int goff = b * HWn + yimg * Wn + xx;
            int loff = yimg * Wn + xx;
            tg[r * FT_STRIDE + 4 + xx] = Hg[goff];
            float sum = (p0[loff] + p1[loff]) + (p2[loff] + p3[loff]);
            float sig = fast_sigmoid(sum);
            tc[r * FT_STRIDE + 4 + xx] = sig;
            if (yimg >= ybase && yimg < ybase + 4) hc[goff] = sig;
        }
    }
    __syncthreads();

    int row = warp >> 1;                // 0..3
    int xh = warp & 1;                  // 0..1
    float* zr = zout + b * HWn + (ybase + row) * Wn;

    #pragma unroll 1
    for (int gi = 0; gi < 2; ++gi) {
        int cb = (xh * 2 + gi) * 32;
        float okeep = 0.0f;
        #pragma unroll 1
        for (int jq = 0; jq < 32; jq += 4) {
            float a0 = bias, a1 = bias, a2 = bias, a3 = bias;
            int c0 = cb + jq;
            #pragma unroll
            for (int half = 0; half < 2; ++half) {
                const float* pl = half ? tc : tg;
                #pragma unroll
                for (int dr = 0; dr < 3; ++dr) {
                    const float* rowp = pl + (row + dr) * FT_STRIDE + 4 + c0;
                    float4 m = *(const float4*)rowp;
                    float lf = rowp[-1];
                    float rt = rowp[4];
                    float t0 = w[half * 9 + dr * 3 + 0];
                    float t1 = w[half * 9 + dr * 3 + 1];
                    float t2 = w[half * 9 + dr * 3 + 2];
                    a0 = fmaf(lf,  t0, fmaf(m.x, t1, fmaf(m.y, t2, a0)));
                    a1 = fmaf(m.x, t0, fmaf(m.y, t1, fmaf(m.z, t2, a1)));
                    a2 = fmaf(m.y, t0, fmaf(m.z, t1, fmaf(m.w, t2, a2)));
                    a3 = fmaf(m.z, t0, fmaf(m.w, t1, fmaf(rt,  t2, a3)));
                }
            }
            float z0 = c2f * (a0 * fast_sigmoid(a0));
            float z1 = c2f * (a1 * fast_sigmoid(a1));
            float z2 = c2f * (a2 * fast_sigmoid(a2));
            float z3 = c2f * (a3 * fast_sigmoid(a3));
            #pragma unroll
            for (int off = 16; off > 0; off >>= 1) {
                z0 += __shfl_xor_sync(0xffffffffu, z0, off);
                z1 += __shfl_xor_sync(0xffffffffu, z1, off);
                z2 += __shfl_xor_sync(0xffffffffu, z2, off);
                z3 += __shfl_xor_sync(0xffffffffu, z3, off);
            }
            float o0 = fast_sigmoid(z0 + sb2);
            float o1 = fast_sigmoid(z1 + sb2);
            float o2 = fast_sigmoid(z2 + sb2);
            float o3 = fast_sigmoid(z3 + sb2);
            if (lane == jq + 0) okeep = o0;
            if (lane == jq + 1) okeep = o1;
            if (lane == jq + 2) okeep = o2;
            if (lane == jq + 3) okeep = o3;
        }
        zr[cb + lane] = okeep;
    }
}

// ============================================================
extern "C" void kernel_launch(void* const* d_in, const int* in_sizes, int n_in,
                              void* d_out, int out_size) {
    const float* Hf   = (const float*)d_in[0];
    const float* hp   = (const float*)d_in[1];
    const float* Hg   = (const float*)d_in[2];
    const float* fc1w = (const float*)d_in[3];
    const float* fc1b = (const float*)d_in[4];
    const float* fc2w = (const float*)d_in[5];
    const float* fc2b = (const float*)d_in[6];
    const float* c1w  = (const float*)d_in[7];
    const float* c1b  = (const float*)d_in[8];
    const float* bng  = (const float*)d_in[9];
    const float* bnb  = (const float*)d_in[10];
    const float* bnm  = (const float*)d_in[11];
    const float* bnv  = (const float*)d_in[12];
    const float* c2w  = (const float*)d_in[13];
    const float* c2b  = (const float*)d_in[14];

    float* out = (float*)d_out;
    float* z  = out + Z_OFF;
    float* hc = out + HC_OFF;
    float* R  = out + R_OFF;

    argmax_kernel<<<Bn, 256>>>(hp);
    extract_kernel<<<dim3(4, Bn), 256>>>(Hf, R);
    fc_kernel<<<Bn, 1024>>>(fc1w, fc1b, fc2w, fc2b);

    cudaFuncSetAttribute(corr_kernel, cudaFuncAttributeMaxDynamicSharedMemorySize, CORR_SMEM);
    corr_kernel<<<dim3(8, Bn), 256, CORR_SMEM>>>(Hf);

    fuse_kernel<<<dim3(16, Bn), 256>>>(Hg, c1w, c1b, bng, bnb, bnm, bnv, c2w, c2b, hc, z);
}